// round 7
// baseline (speedup 1.0000x reference)
#include <cuda_runtime.h>
#include <cuda_fp16.h>

typedef unsigned int u32;

#define NROWS    16384
#define DIM      4096
#define NEXP     64
#define KT       64
#define NCHUNK   (DIM / KT)
#define ROWS_CTA 128
#define NTH      384            // 8 consumer warps + 4 producer warps

#define WSCALE     4096.0f
#define INV_WSCALE (1.0f / 4096.0f)
#define RSC        2048.0f
#define RINV       (1.0f / 2048.0f)

// smem layout (bytes)
#define A_COMP   16384
#define A_STAGE  32768
#define OFF_B    65536
#define B_COMP   8192
#define B_STAGE  16384
#define OFF_BIAS 98304
#define SMEM_BYTES 98560

#define SWZ(o) ((o) ^ (((o) >> 3) & 0x70))

// named barrier IDs: FULL[st] = 1+st (all-384 sync), EMPTY[st] = 3+st
#define BAR_SYNC(id)   asm volatile("bar.sync %0, %1;"   :: "r"(id), "r"(NTH) : "memory")
#define BAR_ARRIVE(id) asm volatile("bar.arrive %0, %1;" :: "r"(id), "r"(NTH) : "memory")

// W pre-split: comp0 = fp16(W*4096), comp1 = fp16((W*4096 - comp0)*2048)
__device__ __half g_Wc[2][NEXP * DIM];

// ---------------- helpers ----------------
__device__ __forceinline__ u32 smem_u32(const void* p) {
    u32 a;
    asm("{ .reg .u64 t; cvta.to.shared.u64 t, %1; cvt.u32.u64 %0, t; }" : "=r"(a) : "l"(p));
    return a;
}

__device__ __forceinline__ void ldsm4(u32* r, u32 addr) {
    asm volatile("ldmatrix.sync.aligned.m8n8.x4.shared.b16 {%0,%1,%2,%3}, [%4];"
                 : "=r"(r[0]), "=r"(r[1]), "=r"(r[2]), "=r"(r[3]) : "r"(addr));
}

__device__ __forceinline__ void mma16816(float* d, const u32* a, u32 b0, u32 b1) {
    asm volatile(
        "mma.sync.aligned.m16n8k16.row.col.f32.f16.f16.f32 "
        "{%0,%1,%2,%3}, {%4,%5,%6,%7}, {%8,%9}, {%0,%1,%2,%3};"
        : "+f"(d[0]), "+f"(d[1]), "+f"(d[2]), "+f"(d[3])
        : "r"(a[0]), "r"(a[1]), "r"(a[2]), "r"(a[3]), "r"(b0), "r"(b1));
}

// split float4 -> hi fp16 comp + UP-SCALED fp16 residual comp
__device__ __forceinline__ void split4(float4 v, uint2& h1, uint2& h2) {
    __half2 p0 = __floats2half2_rn(v.x, v.y);
    __half2 p1 = __floats2half2_rn(v.z, v.w);
    float2 f0 = __half22float2(p0);
    float2 f1 = __half22float2(p1);
    __half2 q0 = __floats2half2_rn((v.x - f0.x) * RSC, (v.y - f0.y) * RSC);
    __half2 q1 = __floats2half2_rn((v.z - f1.x) * RSC, (v.w - f1.y) * RSC);
    h1.x = reinterpret_cast<u32&>(p0);
    h1.y = reinterpret_cast<u32&>(p1);
    h2.x = reinterpret_cast<u32&>(q0);
    h2.y = reinterpret_cast<u32&>(q1);
}

// ---------------- prep: split scaled W into 2 fp16 components ----------------
__global__ void prep_kernel(const float* __restrict__ W) {
    int total = NEXP * DIM / 4;
    for (int idx = blockIdx.x * blockDim.x + threadIdx.x; idx < total;
         idx += gridDim.x * blockDim.x) {
        float4 v = ((const float4*)W)[idx];
        v.x *= WSCALE; v.y *= WSCALE; v.z *= WSCALE; v.w *= WSCALE;
        uint2 h1, h2;
        split4(v, h1, h2);
        ((uint2*)g_Wc[0])[idx] = h1;
        ((uint2*)g_Wc[1])[idx] = h2;
    }
}

// ---------------- main fused kernel ----------------
__global__ __launch_bounds__(NTH, 1)
void gating_mma_kernel(const float* __restrict__ x, const float* __restrict__ bias_g,
                       float* __restrict__ out, int out_size)
{
    extern __shared__ char smem[];
    const u32 sb = smem_u32(smem);
    const int tid = threadIdx.x;
    const int lane = tid & 31;
    const int warp = tid >> 5;
    const int rowBase = blockIdx.x * ROWS_CTA;

    if (tid < NEXP) ((float*)(smem + OFF_BIAS))[tid] = bias_g[tid];

    // consumer state lives at function scope so the epilogue (after reconvergence)
    // can read the accumulators
    float accm[2][4][4], accc[2][4][4];
    const int mrow = (warp & 3) * 32;
    const int ncol = (warp >> 2) * 32;

    if (warp >= 8) {
        // ================= PRODUCER (warps 8-11, 128 threads) =================
        const int pt = tid - 256;
        float4 px[16];
        uint4  pw[8];

        // prefetch chunk 0
#pragma unroll
        for (int i = 0; i < 16; i++) {
            int idx = pt + i * 128;
            int r = idx >> 4, q = idx & 15;
            px[i] = *(const float4*)(x + (size_t)(rowBase + r) * DIM + q * 4);
        }
#pragma unroll
        for (int i = 0; i < 8; i++) {
            int idx = pt + i * 128;
            int comp = idx >> 9, rem = idx & 511, e = rem >> 3, q = rem & 7;
            pw[i] = *(const uint4*)(&g_Wc[comp][(size_t)e * DIM + q * 8]);
        }

        for (int c = 0; c < NCHUNK; c++) {
            const int st = c & 1;
            if (c >= 2) BAR_SYNC(3 + st);       // wait stage free
            char* As = smem + st * A_STAGE;
            char* Bs = smem + OFF_B + st * B_STAGE;

#pragma unroll
            for (int i = 0; i < 16; i++) {
                int idx = pt + i * 128;
                int r = idx >> 4, q = idx & 15;
                uint2 h1, h2;
                split4(px[i], h1, h2);
                u32 off = SWZ((u32)(r * 128 + q * 8));
                *(uint2*)(As + off) = h1;
                *(uint2*)(As + A_COMP + off) = h2;
            }
#pragma unroll
            for (int i = 0; i < 8; i++) {
                int idx = pt + i * 128;
                int comp = idx >> 9, rem = idx & 511, e = rem >> 3, q = rem & 7;
                u32 off = SWZ((u32)(e * 128 + q * 16));
                *(uint4*)(Bs + comp * B_COMP + off) = pw[i];
            }
            BAR_SYNC(1 + st);                   // publish stage (full sync = ordering)

            if (c + 1 < NCHUNK) {
                const float* xc = x + (size_t)rowBase * DIM + (c + 1) * KT;
#pragma unroll
                for (int i = 0; i < 16; i++) {
                    int idx = pt + i * 128;
                    int r = idx >> 4, q = idx & 15;
                    px[i] = *(const float4*)(xc + (size_t)r * DIM + q * 4);
                }
#pragma unroll
                for (int i = 0; i < 8; i++) {
                    int idx = pt + i * 128;
                    int comp = idx >> 9, rem = idx & 511, e = rem >> 3, q = rem & 7;
                    pw[i] = *(const uint4*)(&g_Wc[comp][(size_t)e * DIM + (c + 1) * KT + q * 8]);
                }
            }
        }
    } else {
        // ================= CONSUMER (warps 0-7, 256 threads) =================
#pragma unroll
        for (int mt = 0; mt < 2; mt++)
#pragma unroll
            for (int nt = 0; nt < 4; nt++)
#pragma unroll
                for (int j = 0; j < 4; j++) { accm[mt][nt][j] = 0.0f; accc[mt][nt][j] = 0.0f; }

        const int a_row  = (lane & 7) + 8 * ((lane >> 3) & 1);
        const int a_koff = (lane >> 4) * 8;
        // B ldmatrix lane geometry: 4 groups of 8 lanes = 4 8x8 matrices
        const int g  = lane >> 3, lr = lane & 7;
        const int be  = ((g >= 2) ? 8 : 0) + lr;   // expert row within 16-row pair
        const int bko = (g & 1) ? 16 : 0;          // k byte offset (k+8 halves)

        for (int c = 0; c < NCHUNK; c++) {
            const int st = c & 1;
            BAR_SYNC(1 + st);                   // wait stage full
            const u32 sA  = sb + st * A_STAGE;
            const u32 sB1 = sb + OFF_B + st * B_STAGE;
            const u32 sB2 = sB1 + B_COMP;

#pragma unroll
            for (int kc = 0; kc < 4; kc++) {
                u32 a1[2][4], a2[2][4];
#pragma unroll
                for (int mt = 0; mt < 2; mt++) {
                    u32 off = SWZ((u32)((mrow + mt * 16 + a_row) * 128 + kc * 32 + a_koff * 2));
                    ldsm4(a1[mt], sA + off);
                    ldsm4(a2[mt], sA + A_COMP + off);
                }
                u32 b1[2][4], b2[2][4];
#pragma unroll
                for (int p = 0; p < 2; p++) {
                    u32 off = SWZ((u32)((ncol + p * 16 + be) * 128 + kc * 32 + bko));
                    ldsm4(b1[p], sB1 + off);
                    ldsm4(b2[p], sB2 + off);
                }
#pragma unroll
                for (int nt = 0; nt < 4; nt++) {
                    int p = nt >> 1, o = (nt & 1) * 2;
                    u32 b10 = b1[p][o], b11 = b1[p][o + 1];
                    u32 b20 = b2[p][o], b21 = b2[p][o + 1];
                    mma16816(accm[0][nt], a1[0], b10, b11);
                    mma16816(accm[1][nt], a1[1], b10, b11);
                    mma16816(accc[0][nt], a1[0], b20, b21);
                    mma16816(accc[1][nt], a1[1], b20, b21);
                    mma16816(accc[0][nt], a2[0], b10, b11);
                    mma16816(accc[1][nt], a2[1], b10, b11);
                }
            }
            BAR_ARRIVE(3 + st);                 // release stage
        }
    }

    // ---- reconvergence; epilogue ----
    __syncthreads();

    float (*lg)[66] = (float(*)[66])smem;       // 128 x 66 f32 overlay (33792 B)
    if (warp < 8) {
#pragma unroll
        for (int mt = 0; mt < 2; mt++)
#pragma unroll
            for (int nt = 0; nt < 4; nt++) {
                int r0 = mrow + mt * 16 + (lane >> 2);
                int cb = ncol + nt * 8 + 2 * (lane & 3);
                float c0 = fmaf(accc[mt][nt][0], RINV, accm[mt][nt][0]);
                float c1 = fmaf(accc[mt][nt][1], RINV, accm[mt][nt][1]);
                float c2 = fmaf(accc[mt][nt][2], RINV, accm[mt][nt][2]);
                float c3 = fmaf(accc[mt][nt][3], RINV, accm[mt][nt][3]);
                *(float2*)&lg[r0][cb]     = make_float2(c0, c1);
                *(float2*)&lg[r0 + 8][cb] = make_float2(c2, c3);
            }
    }
    __syncthreads();

    if (tid < ROWS_CTA) {
        const float* bs = (const float*)(smem + OFF_BIAS);
        float v0 = -3.402823466e38f, v1 = -3.402823466e38f;
        int i0 = 0, i1 = 0;
#pragma unroll
        for (int e = 0; e < NEXP; e++) {
            float v = fmaf(lg[tid][e], INV_WSCALE, bs[e]);
            if (v > v0) { v1 = v0; i1 = i0; v0 = v; i0 = e; }
            else if (v > v1) { v1 = v; i1 = e; }
        }
        float d  = expf(v1 - v0);
        float p0 = 1.0f / (1.0f + d);
        float p1 = d / (1.0f + d);

        int grow = rowBase + tid;
        float* orow = out + (size_t)grow * NEXP;
#pragma unroll
        for (int gq = 0; gq < NEXP / 4; gq++) {
            float4 ov;
            int e = gq * 4;
            ov.x = (e + 0 == i0) ? p0 : ((e + 0 == i1) ? p1 : 0.0f);
            ov.y = (e + 1 == i0) ? p0 : ((e + 1 == i1) ? p1 : 0.0f);
            ov.z = (e + 2 == i0) ? p0 : ((e + 2 == i1) ? p1 : 0.0f);
            ov.w = (e + 3 == i0) ? p0 : ((e + 3 == i1) ? p1 : 0.0f);
            *(float4*)(orow + e) = ov;
        }
        if (out_size >= NROWS * (NEXP + 2)) {
            float* oidx = out + (size_t)NROWS * NEXP + (size_t)grow * 2;
            oidx[0] = (float)i0;
            oidx[1] = (float)i1;
        }
    }
}

extern "C" void kernel_launch(void* const* d_in, const int* in_sizes, int n_in,
                              void* d_out, int out_size) {
    const float* x = nullptr;
    const float* W = nullptr;
    const float* b = nullptr;
    for (int i = 0; i < n_in; i++) {
        if (in_sizes[i] == NROWS * DIM)      x = (const float*)d_in[i];
        else if (in_sizes[i] == NEXP * DIM)  W = (const float*)d_in[i];
        else if (in_sizes[i] == NEXP)        b = (const float*)d_in[i];
    }
    cudaFuncSetAttribute(gating_mma_kernel, cudaFuncAttributeMaxDynamicSharedMemorySize,
                         SMEM_BYTES);
    prep_kernel<<<128, 256>>>(W);
    gating_mma_kernel<<<NROWS / ROWS_CTA, NTH, SMEM_BYTES>>>(x, b, (float*)d_out, out_size);
}

// round 8
// speedup vs baseline: 1.0994x; 1.0994x over previous
#include <cuda_runtime.h>
#include <cuda_fp16.h>

typedef unsigned int u32;

#define NROWS    16384
#define DIM      4096
#define NEXP     64
#define KT       64
#define NCHUNK   (DIM / KT)
#define ROWS_CTA 128
#define NTH      512            // 16 warps, all cooperative (R5 structure, 2x warps)

#define WSCALE     4096.0f
#define INV_WSCALE (1.0f / 4096.0f)
#define RSC        2048.0f
#define RINV       (1.0f / 2048.0f)

// smem layout (bytes)
#define A_COMP   16384
#define A_STAGE  32768
#define OFF_B    65536
#define B_COMP   8192
#define B_STAGE  16384
#define OFF_BIAS 98304
#define SMEM_BYTES 98560

#define SWZ(o) ((o) ^ (((o) >> 3) & 0x70))

// W pre-split: comp0 = fp16(W*4096), comp1 = fp16((W*4096 - comp0)*2048)
__device__ __half g_Wc[2][NEXP * DIM];

// ---------------- helpers ----------------
__device__ __forceinline__ u32 smem_u32(const void* p) {
    u32 a;
    asm("{ .reg .u64 t; cvta.to.shared.u64 t, %1; cvt.u32.u64 %0, t; }" : "=r"(a) : "l"(p));
    return a;
}

__device__ __forceinline__ void ldsm4(u32* r, u32 addr) {
    asm volatile("ldmatrix.sync.aligned.m8n8.x4.shared.b16 {%0,%1,%2,%3}, [%4];"
                 : "=r"(r[0]), "=r"(r[1]), "=r"(r[2]), "=r"(r[3]) : "r"(addr));
}

__device__ __forceinline__ void mma16816(float* d, const u32* a, u32 b0, u32 b1) {
    asm volatile(
        "mma.sync.aligned.m16n8k16.row.col.f32.f16.f16.f32 "
        "{%0,%1,%2,%3}, {%4,%5,%6,%7}, {%8,%9}, {%0,%1,%2,%3};"
        : "+f"(d[0]), "+f"(d[1]), "+f"(d[2]), "+f"(d[3])
        : "r"(a[0]), "r"(a[1]), "r"(a[2]), "r"(a[3]), "r"(b0), "r"(b1));
}

// split float4 -> hi fp16 comp + UP-SCALED fp16 residual comp
__device__ __forceinline__ void split4(float4 v, uint2& h1, uint2& h2) {
    __half2 p0 = __floats2half2_rn(v.x, v.y);
    __half2 p1 = __floats2half2_rn(v.z, v.w);
    float2 f0 = __half22float2(p0);
    float2 f1 = __half22float2(p1);
    __half2 q0 = __floats2half2_rn((v.x - f0.x) * RSC, (v.y - f0.y) * RSC);
    __half2 q1 = __floats2half2_rn((v.z - f1.x) * RSC, (v.w - f1.y) * RSC);
    h1.x = reinterpret_cast<u32&>(p0);
    h1.y = reinterpret_cast<u32&>(p1);
    h2.x = reinterpret_cast<u32&>(q0);
    h2.y = reinterpret_cast<u32&>(q1);
}

// ---------------- prep: split scaled W into 2 fp16 components ----------------
__global__ void prep_kernel(const float* __restrict__ W) {
    int total = NEXP * DIM / 4;
    for (int idx = blockIdx.x * blockDim.x + threadIdx.x; idx < total;
         idx += gridDim.x * blockDim.x) {
        float4 v = ((const float4*)W)[idx];
        v.x *= WSCALE; v.y *= WSCALE; v.z *= WSCALE; v.w *= WSCALE;
        uint2 h1, h2;
        split4(v, h1, h2);
        ((uint2*)g_Wc[0])[idx] = h1;
        ((uint2*)g_Wc[1])[idx] = h2;
    }
}

// ---------------- main fused kernel ----------------
__global__ __launch_bounds__(NTH, 1)
void gating_mma_kernel(const float* __restrict__ x, const float* __restrict__ bias_g,
                       float* __restrict__ out, int out_size)
{
    extern __shared__ char smem[];
    const u32 sb = smem_u32(smem);
    const int tid = threadIdx.x;
    const int lane = tid & 31;
    const int warp = tid >> 5;
    const int rowBase = blockIdx.x * ROWS_CTA;

    // warp tile m16n32: 8 row-groups x 2 col-groups
    const int mrow = (warp & 7) * 16;
    const int ncol = (warp >> 3) * 32;

    if (tid < NEXP) ((float*)(smem + OFF_BIAS))[tid] = bias_g[tid];

    // ---- register prefetch buffers (per-thread share shrinks with 512 thr) ----
    float4 px[4];   // 2048 float4 / 512
    uint4  pw[2];   // 1024 uint4-chunks / 512

#pragma unroll
    for (int i = 0; i < 4; i++) {
        int idx = tid + i * NTH;
        int r = idx >> 4, q = idx & 15;
        px[i] = *(const float4*)(x + (size_t)(rowBase + r) * DIM + q * 4);
    }
#pragma unroll
    for (int i = 0; i < 2; i++) {
        int idx = tid + i * NTH;
        int comp = idx >> 9, rem = idx & 511, e = rem >> 3, q = rem & 7;
        pw[i] = *(const uint4*)(&g_Wc[comp][(size_t)e * DIM + q * 8]);
    }

    // main accumulator (x1*w1) and correction accumulator (x1*w2' + x2'*w1)
    float accm[4][4], accc[4][4];
#pragma unroll
    for (int nt = 0; nt < 4; nt++)
#pragma unroll
        for (int j = 0; j < 4; j++) { accm[nt][j] = 0.0f; accc[nt][j] = 0.0f; }

    // A ldmatrix lane geometry (m16k16 via x4)
    const int a_row  = lane & 15;
    const int a_koff = (lane >> 4) * 8;
    // B ldmatrix lane geometry (verified in R6: identical rel_err)
    const int g  = lane >> 3, lr = lane & 7;
    const int be  = ((g >= 2) ? 8 : 0) + lr;
    const int bko = (g & 1) ? 16 : 0;

    for (int c = 0; c < NCHUNK; c++) {
        const int st = c & 1;
        char* As = smem + st * A_STAGE;
        char* Bs = smem + OFF_B + st * B_STAGE;

        // ---- STS: convert x to 2 fp16 comps, store W comps, swizzled ----
#pragma unroll
        for (int i = 0; i < 4; i++) {
            int idx = tid + i * NTH;
            int r = idx >> 4, q = idx & 15;
            uint2 h1, h2;
            split4(px[i], h1, h2);
            u32 off = SWZ((u32)(r * 128 + q * 8));
            *(uint2*)(As + off) = h1;
            *(uint2*)(As + A_COMP + off) = h2;
        }
#pragma unroll
        for (int i = 0; i < 2; i++) {
            int idx = tid + i * NTH;
            int comp = idx >> 9, rem = idx & 511, e = rem >> 3, q = rem & 7;
            u32 off = SWZ((u32)(e * 128 + q * 16));
            *(uint4*)(Bs + comp * B_COMP + off) = pw[i];
        }
        __syncthreads();

        // ---- prefetch next chunk into regs (hidden behind mma) ----
        if (c + 1 < NCHUNK) {
            const float* xc = x + (size_t)rowBase * DIM + (c + 1) * KT;
#pragma unroll
            for (int i = 0; i < 4; i++) {
                int idx = tid + i * NTH;
                int r = idx >> 4, q = idx & 15;
                px[i] = *(const float4*)(xc + (size_t)r * DIM + q * 4);
            }
#pragma unroll
            for (int i = 0; i < 2; i++) {
                int idx = tid + i * NTH;
                int comp = idx >> 9, rem = idx & 511, e = rem >> 3, q = rem & 7;
                pw[i] = *(const uint4*)(&g_Wc[comp][(size_t)e * DIM + (c + 1) * KT + q * 8]);
            }
        }

        // ---- mma: 3 passes, dual accumulators, ldmatrix for A and B ----
        const u32 sA  = sb + st * A_STAGE;
        const u32 sB1 = sb + OFF_B + st * B_STAGE;
        const u32 sB2 = sB1 + B_COMP;
#pragma unroll
        for (int kc = 0; kc < 4; kc++) {
            u32 a1[4], a2[4];
            {
                u32 off = SWZ((u32)((mrow + a_row) * 128 + kc * 32 + a_koff * 2));
                ldsm4(a1, sA + off);
                ldsm4(a2, sA + A_COMP + off);
            }
            u32 b1[2][4], b2[2][4];
#pragma unroll
            for (int p = 0; p < 2; p++) {
                u32 off = SWZ((u32)((ncol + p * 16 + be) * 128 + kc * 32 + bko));
                ldsm4(b1[p], sB1 + off);
                ldsm4(b2[p], sB2 + off);
            }
#pragma unroll
            for (int nt = 0; nt < 4; nt++) {
                int p = nt >> 1, o = (nt & 1) * 2;
                u32 b10 = b1[p][o], b11 = b1[p][o + 1];
                u32 b20 = b2[p][o], b21 = b2[p][o + 1];
                mma16816(accm[nt], a1, b10, b11);
                mma16816(accc[nt], a1, b20, b21);
                mma16816(accc[nt], a2, b10, b11);
            }
        }
    }

    // ---- epilogue: combine accumulators, logits -> smem overlay, fused top-2 ----
    __syncthreads();
    float (*lg)[66] = (float(*)[66])smem;
#pragma unroll
    for (int nt = 0; nt < 4; nt++) {
        int r0 = mrow + (lane >> 2);
        int cb = ncol + nt * 8 + 2 * (lane & 3);
        float c0 = fmaf(accc[nt][0], RINV, accm[nt][0]);
        float c1 = fmaf(accc[nt][1], RINV, accm[nt][1]);
        float c2 = fmaf(accc[nt][2], RINV, accm[nt][2]);
        float c3 = fmaf(accc[nt][3], RINV, accm[nt][3]);
        *(float2*)&lg[r0][cb]     = make_float2(c0, c1);
        *(float2*)&lg[r0 + 8][cb] = make_float2(c2, c3);
    }
    __syncthreads();

    if (tid < ROWS_CTA) {
        const float* bs = (const float*)(smem + OFF_BIAS);
        float v0 = -3.402823466e38f, v1 = -3.402823466e38f;
        int i0 = 0, i1 = 0;
#pragma unroll
        for (int e = 0; e < NEXP; e++) {
            float v = fmaf(lg[tid][e], INV_WSCALE, bs[e]);
            if (v > v0) { v1 = v0; i1 = i0; v0 = v; i0 = e; }
            else if (v > v1) { v1 = v; i1 = e; }
        }
        float d  = expf(v1 - v0);
        float p0 = 1.0f / (1.0f + d);
        float p1 = d / (1.0f + d);

        int grow = rowBase + tid;
        float* orow = out + (size_t)grow * NEXP;
#pragma unroll
        for (int gq = 0; gq < NEXP / 4; gq++) {
            float4 ov;
            int e = gq * 4;
            ov.x = (e + 0 == i0) ? p0 : ((e + 0 == i1) ? p1 : 0.0f);
            ov.y = (e + 1 == i0) ? p0 : ((e + 1 == i1) ? p1 : 0.0f);
            ov.z = (e + 2 == i0) ? p0 : ((e + 2 == i1) ? p1 : 0.0f);
            ov.w = (e + 3 == i0) ? p0 : ((e + 3 == i1) ? p1 : 0.0f);
            *(float4*)(orow + e) = ov;
        }
        if (out_size >= NROWS * (NEXP + 2)) {
            float* oidx = out + (size_t)NROWS * NEXP + (size_t)grow * 2;
            oidx[0] = (float)i0;
            oidx[1] = (float)i1;
        }
    }
}

extern "C" void kernel_launch(void* const* d_in, const int* in_sizes, int n_in,
                              void* d_out, int out_size) {
    const float* x = nullptr;
    const float* W = nullptr;
    const float* b = nullptr;
    for (int i = 0; i < n_in; i++) {
        if (in_sizes[i] == NROWS * DIM)      x = (const float*)d_in[i];
        else if (in_sizes[i] == NEXP * DIM)  W = (const float*)d_in[i];
        else if (in_sizes[i] == NEXP)        b = (const float*)d_in[i];
    }
    cudaFuncSetAttribute(gating_mma_kernel, cudaFuncAttributeMaxDynamicSharedMemorySize,
                         SMEM_BYTES);
    prep_kernel<<<128, 256>>>(W);
    gating_mma_kernel<<<NROWS / ROWS_CTA, NTH, SMEM_BYTES>>>(x, b, (float*)d_out, out_size);
}